// round 8
// baseline (speedup 1.0000x reference)
#include <cuda_runtime.h>
#include <math.h>

// input:  (B=2, T=2048, V=32000) f32 ; target: (2, 2048) int32 ; out: scalar f32
// ct_len = 512, win = 256
#define B_DIM 2
#define T_DIM 2048
#define V_DIM 32000
#define CT_LEN 512
#define WIN 256
#define ROWS (B_DIM * CT_LEN)      // 1024
#define IGNORE_INDEX (-100)
#define PAD_ID 0

#define WARPS_PER_CTA 8
#define CTA_THREADS (WARPS_PER_CTA * 32)      // 256
#define GRID_CTAS (ROWS / WARPS_PER_CTA)      // 128
#define NEGS_PER_LANE (WIN / 32)              // 8

// Allocation-free accumulators. Last CTA resets them each call, and graph
// replays are stream-serialized, so every replay starts from zero.
__device__ float        g_loss_sum  = 0.0f;
__device__ float        g_valid_sum = 0.0f;
__device__ unsigned int g_done      = 0u;

__global__ __launch_bounds__(CTA_THREADS, 8)
void ctl_warp_kernel(const float* __restrict__ input,
                     const int* __restrict__ target,
                     float* __restrict__ out)
{
    const int tid  = threadIdx.x;
    const int lane = tid & 31;
    const int w    = tid >> 5;
    const int row  = blockIdx.x * WARPS_PER_CTA + w;  // 0..1023
    const int b    = row >> 9;                        // / CT_LEN
    const int i    = row & (CT_LEN - 1);

    const int tbase = b * T_DIM;
    const long long lbase = ((long long)(b * T_DIM + i)) * V_DIM;

    // --- batch 1: coalesced target loads + row target (broadcast) ---
    const int t = __ldg(&target[tbase + i]);
    int tj[NEGS_PER_LANE];
    #pragma unroll
    for (int k = 0; k < NEGS_PER_LANE; k++) {
        const int j = i - WIN + k * 32 + lane;
        tj[k] = (j >= 0) ? __ldg(&target[tbase + j]) : PAD_ID;
    }

    const int vrow = (t != IGNORE_INDEX);
    int ts = vrow ? t : PAD_ID;
    ts = ts < 0 ? 0 : (ts >= V_DIM ? V_DIM - 1 : ts);

    // --- batch 2: pos (warp-broadcast) + 8 independent gathers, all in flight ---
    const float pos = __ldg(&input[lbase + ts]);
    float nv[NEGS_PER_LANE];
    #pragma unroll
    for (int k = 0; k < NEGS_PER_LANE; k++) {
        int c = tj[k];
        int idx = c < 0 ? 0 : (c >= V_DIM ? V_DIM - 1 : c);  // PAD/j<0 -> idx 0 (cheap broadcast)
        nv[k] = __ldg(&input[lbase + idx]);
    }

    // --- compute + warp reduction (no barriers in hot path) ---
    float e = 0.0f;
    #pragma unroll
    for (int k = 0; k < NEGS_PER_LANE; k++) {
        if (tj[k] != PAD_ID)                      // j<0 lanes have tj==PAD -> excluded
            e += __expf(nv[k] - pos);
    }
    #pragma unroll
    for (int o = 16; o > 0; o >>= 1)
        e += __shfl_down_sync(0xffffffffu, e, o);

    // Per-row contribution straight into global accumulators (overlaps with
    // other CTAs' gather drain; no scratch pass, no extra dependent read).
    if (lane == 0) {
        if (vrow) {
            atomicAdd(&g_loss_sum, log1pf(e));
            atomicAdd(&g_valid_sum, 1.0f);
        }
    }

    // --- ticket: last CTA finalizes ---
    __shared__ int s_last;
    __syncthreads();
    if (tid == 0) {
        __threadfence();
        unsigned int ticket = atomicAdd(&g_done, 1u);
        s_last = (ticket == (unsigned int)(GRID_CTAS - 1));
    }
    __syncthreads();

    if (s_last && tid == 0) {
        __threadfence();
        float l = g_loss_sum;
        float v = g_valid_sum;
        out[0] = l / fmaxf(v, 1.0f);
        // reset for next graph replay (replays are stream-serialized)
        g_loss_sum  = 0.0f;
        g_valid_sum = 0.0f;
        g_done      = 0u;
    }
}

extern "C" void kernel_launch(void* const* d_in, const int* in_sizes, int n_in,
                              void* d_out, int out_size)
{
    const float* input  = (const float*)d_in[0];
    const int*   target = (const int*)d_in[1];
    float*       out    = (float*)d_out;

    (void)in_sizes; (void)n_in; (void)out_size;

    ctl_warp_kernel<<<GRID_CTAS, CTA_THREADS>>>(input, target, out);
}